// round 16
// baseline (speedup 1.0000x reference)
#include <cuda_runtime.h>
#include <math.h>

#define BB 16
#define NN 8192
#define KK 128
#define MM (NN + KK)          // 8320
#define NCH 260               // 32-roi chunks per batch (260*32 == 8320)
#define NBLK 33               // blocks per batch
#define FULLMASK 0xffffffffu

__device__ int g_cnt[BB * NCH];            // fg count per 32-chunk
__device__ volatile int g_ready[BB];       // blocks-arrived per batch (memset each launch)

// ---------------------------------------------------------------------------
// Fused kernel: IoU argmax (division-free) + per-batch handshake + local scan
// + scatter. One block = (batch b, 256-roi chunk c). All 528 blocks fit in
// one wave (<=64 regs, 4 blocks/SM), so the per-batch spin cannot deadlock.
// ---------------------------------------------------------------------------
__global__ void __launch_bounds__(256, 4)
ptl_fused_kernel(const float* __restrict__ rois_in,  // (B,N,5)
                 const float* __restrict__ gt_in,    // (B,K,5)
                 float* __restrict__ out_rois,       // (B,M,5)
                 float* __restrict__ out_lab,        // (B,M)
                 float4* __restrict__ out_tgt,       // (B,M) float4
                 float4* __restrict__ out_inw,       // (B,M) float4
                 float4* __restrict__ out_outw)      // (B,M) float4
{
    const int b    = blockIdx.y;
    const int c    = blockIdx.x;        // 256-roi chunk, 0..32
    const int tid  = threadIdx.x;
    const int lane = tid & 31;
    const int w    = tid >> 5;

    __shared__ float4 sbox[KK];         // raw {x1, y1, x2, y2}
    __shared__ float  sarea[KK];        // gt area (inf if zero-area)
    __shared__ float  sroi[256 * 5];
    __shared__ float  sgtraw[KK * 5];   // kept for scatter phase (incl. class)
    __shared__ int    s_choff[8];       // exclusive fg prefix for our 8 chunks
    __shared__ int    s_tot;            // total fg for batch

    const float* gtb = gt_in + (size_t)b * KK * 5;
    for (int i = tid; i < KK * 5; i += 256) sgtraw[i] = gtb[i];

    const int mbase = c * 256;
    {   // stage this block's rois coalesced into shared
        int lim = (NN - mbase) * 5;
        if (lim > 256 * 5) lim = 256 * 5;
        if (lim < 0) lim = 0;
        const float* rb = rois_in + ((size_t)b * NN + mbase) * 5;
        for (int i = tid; i < lim; i += 256) sroi[i] = rb[i];
    }
    __syncthreads();

    if (tid < KK) {
        float x1 = sgtraw[tid * 5 + 0];
        float y1 = sgtraw[tid * 5 + 1];
        float x2 = sgtraw[tid * 5 + 2];
        float y2 = sgtraw[tid * 5 + 3];
        float gw = x2 - x1 + 1.0f;
        float gh = y2 - y1 + 1.0f;
        float a  = gw * gh;
        if (gw == 1.0f && gh == 1.0f) a = __int_as_float(0x7f800000);
        sbox[tid]  = make_float4(x1, y1, x2, y2);
        sarea[tid] = a;
    }
    __syncthreads();

    const int  m     = mbase + tid;
    const bool valid = (m < MM);

    float x1, y1, x2, y2;
    if (m < NN) {
        const int li = tid * 5;
        x1 = sroi[li + 1]; y1 = sroi[li + 2];
        x2 = sroi[li + 3]; y2 = sroi[li + 4];
    } else if (valid) {
        float4 g = sbox[m - NN];
        x1 = g.x; y1 = g.y; x2 = g.z; y2 = g.w;
    } else {
        x1 = 0.0f; y1 = 0.0f; x2 = 0.0f; y2 = 0.0f;
    }

    const float aw = x2 - x1 + 1.0f;
    const float ah = y2 - y1 + 1.0f;
    const float areaA = aw * ah;
    const bool  az = (aw == 1.0f) && (ah == 1.0f);

    // 4 independent (num, den, k) chains; division-free cross-mult compare.
    float n0 = -1.0f, d0 = 1.0f, n1 = -1.0f, d1 = 1.0f;
    float n2 = -1.0f, d2 = 1.0f, n3 = -1.0f, d3 = 1.0f;
    int   k0 = 0, k1 = 1, k2 = 2, k3 = 3;

#pragma unroll 4
    for (int k = 0; k < KK; k += 4) {
#pragma unroll
        for (int j = 0; j < 4; j++) {
            const float4 g  = sbox[k + j];
            const float  ga = sarea[k + j];
            float iw = fminf(x2, g.z) - fmaxf(x1, g.x) + 1.0f;
            float ih = fminf(y2, g.w) - fmaxf(y1, g.y) + 1.0f;
            iw = fmaxf(iw, 0.0f);
            ih = fmaxf(ih, 0.0f);
            const float inter = iw * ih;
            const float den = areaA + ga - inter;
            if (j == 0) { if (inter * d0 > n0 * den) { n0 = inter; d0 = den; k0 = k;     } }
            if (j == 1) { if (inter * d1 > n1 * den) { n1 = inter; d1 = den; k1 = k + 1; } }
            if (j == 2) { if (inter * d2 > n2 * den) { n2 = inter; d2 = den; k2 = k + 2; } }
            if (j == 3) { if (inter * d3 > n3 * den) { n3 = inter; d3 = den; k3 = k + 3; } }
        }
    }

    // merge chains: strictly greater, or exact tie -> smaller k (first max)
    {
        const float p10 = n1 * d0, p01 = n0 * d1;
        if (p10 > p01 || (p10 == p01 && k1 < k0)) { n0 = n1; d0 = d1; k0 = k1; }
        const float p32 = n3 * d2, p23 = n2 * d3;
        if (p32 > p23 || (p32 == p23 && k3 < k2)) { n2 = n3; d2 = d3; k2 = k3; }
        const float p20 = n2 * d0, p02 = n0 * d2;
        if (p20 > p02 || (p20 == p02 && k2 < k0)) { n0 = n2; d0 = d2; k0 = k2; }
    }

    // single IEEE divide -> exact reference quotient for the winner
    float bst = n0 / d0;
    int   bestk = k0;
    if (az) { bst = -1.0f; bestk = 0; }
    const bool fg = valid && (bst >= 0.5f);

    // inside/outside weights (original roi order) can go out immediately
    if (valid) {
        const float focal = fg ? (1.0f - bst) * (1.0f - bst) : 0.0f;
        const float ow    = (focal > 0.0f) ? 1.0f : 0.0f;
        out_inw [(size_t)b * MM + m] = make_float4(focal, focal, focal, focal);
        out_outw[(size_t)b * MM + m] = make_float4(ow, ow, ow, ow);
    }

    // publish per-warp (32-roi chunk) fg counts
    const unsigned bal = __ballot_sync(FULLMASK, fg);
    const int wpre = __popc(bal & ((1u << lane) - 1u));
    const int chunk = c * 8 + w;
    if (lane == 0 && chunk < NCH) g_cnt[b * NCH + chunk] = __popc(bal);
    __syncthreads();

    // handshake: signal this block done, wait for all 33 blocks of batch b
    if (tid == 0) {
        __threadfence();
        atomicAdd((int*)&g_ready[b], 1);
        while (g_ready[b] < NBLK) { }
        __threadfence();
    }
    __syncthreads();

    // warp 0: scan the 260 chunk counts; keep prefixes for our 8 chunks + tot
    if (w == 0) {
        int carry = 0;
        const int lo = c * 8, hi = c * 8 + 8;
        for (int base = 0; base < NCH; base += 32) {
            const int idx = base + lane;
            int v = (idx < NCH) ? g_cnt[b * NCH + idx] : 0;
            int s = v;
#pragma unroll
            for (int off = 1; off < 32; off <<= 1) {
                int t = __shfl_up_sync(FULLMASK, s, off);
                if (lane >= off) s += t;
            }
            if (idx >= lo && idx < hi) s_choff[idx - lo] = carry + s - v;
            carry += __shfl_sync(FULLMASK, s, 31);
        }
        if (lane == 0) s_tot = carry;
    }
    __syncthreads();

    // scatter: everything still in registers / smem
    if (valid) {
        const int prefix = s_choff[w] + wpre;              // #fg in [0, m)
        const int totfg  = s_tot;
        const int dest   = fg ? prefix : (totfg + (m - prefix));

        const size_t ro = ((size_t)b * MM + dest) * 5;
        out_rois[ro + 0] = (float)b;
        out_rois[ro + 1] = x1;
        out_rois[ro + 2] = y1;
        out_rois[ro + 3] = x2;
        out_rois[ro + 4] = y2;

        const float cls = sgtraw[bestk * 5 + 4];
        const float lab = fg ? cls : 0.0f;
        out_lab[(size_t)b * MM + dest] = lab;

        float t0 = 0.0f, t1 = 0.0f, t2 = 0.0f, t3 = 0.0f;
        if (lab > 0.0f) {
            const float gx1 = sgtraw[bestk * 5 + 0];
            const float gy1 = sgtraw[bestk * 5 + 1];
            const float gx2 = sgtraw[bestk * 5 + 2];
            const float gy2 = sgtraw[bestk * 5 + 3];
            const float ew  = x2 - x1 + 1.0f;
            const float eh  = y2 - y1 + 1.0f;
            const float ecx = x1 + 0.5f * ew;
            const float ecy = y1 + 0.5f * eh;
            const float gw  = gx2 - gx1 + 1.0f;
            const float gh  = gy2 - gy1 + 1.0f;
            const float gcx = gx1 + 0.5f * gw;
            const float gcy = gy1 + 0.5f * gh;
            t0 = ((gcx - ecx) / ew) / 0.1f;
            t1 = ((gcy - ecy) / eh) / 0.1f;
            t2 = logf(gw / ew) / 0.2f;
            t3 = logf(gh / eh) / 0.2f;
        }
        out_tgt[(size_t)b * MM + dest] = make_float4(t0, t1, t2, t3);
    }
}

// ---------------------------------------------------------------------------
extern "C" void kernel_launch(void* const* d_in, const int* in_sizes, int n_in,
                              void* d_out, int out_size)
{
    const float* rois = (const float*)d_in[0];   // (16, 8192, 5) f32
    const float* gt   = (const float*)d_in[1];   // (16, 128, 5) f32
    float* out = (float*)d_out;

    // outputs concatenated in reference tuple order
    float* out_rois = out;                                   // B*M*5
    float* out_lab  = out_rois + (size_t)BB * MM * 5;        // B*M
    float* out_tgt  = out_lab  + (size_t)BB * MM;            // B*M*4
    float* out_inw  = out_tgt  + (size_t)BB * MM * 4;        // B*M*4
    float* out_outw = out_inw  + (size_t)BB * MM * 4;        // B*M*4

    // reset the per-batch arrival flags (graph-capturable memset node)
    void* ready_addr = nullptr;
    cudaGetSymbolAddress(&ready_addr, g_ready);
    cudaMemsetAsync(ready_addr, 0, BB * sizeof(int));

    dim3 g(NBLK, BB);
    ptl_fused_kernel<<<g, 256>>>(rois, gt, out_rois, out_lab,
                                 (float4*)out_tgt, (float4*)out_inw,
                                 (float4*)out_outw);
}

// round 17
// speedup vs baseline: 1.6056x; 1.6056x over previous
#include <cuda_runtime.h>
#include <math.h>

#define BB 16
#define NN 8192
#define KK 128
#define MM (NN + KK)          // 8320
#define NCH 260               // 32-roi chunks per batch (260*32 == 8320)
#define FULLMASK 0xffffffffu

__device__ int g_cnt[BB * NCH];  // fg count per 32-chunk
// scratch: bestk (bits 0..7) | fg flag (bit 8), per (b, m)
__device__ int g_combo[BB * MM];

// ---------------------------------------------------------------------------
// K1: thread-per-roi IoU argmax, division-free inner loop, 128-thread blocks
// for high occupancy (1040 blocks -> ~56 warps/SM). 65*128 == MM exactly so
// every thread is valid. 4 independent (num,den,k) chains; the 128 IEEE
// divides collapse to ONE final divide for the winner (exact reference
// quotient). Geometry bit-faithful: +1 AFTER min/max subtraction.
// ---------------------------------------------------------------------------
__global__ void __launch_bounds__(128)
ptl_iou_kernel(const float* __restrict__ rois_in,  // (B,N,5)
               const float* __restrict__ gt_in,    // (B,K,5)
               float4* __restrict__ out_inw,       // (B,M) float4
               float4* __restrict__ out_outw)      // (B,M) float4
{
    const int b    = blockIdx.y;
    const int c    = blockIdx.x;        // 128-roi chunk, 0..64
    const int tid  = threadIdx.x;
    const int lane = tid & 31;
    const int w    = tid >> 5;

    __shared__ float4 sbox[KK];         // raw {x1, y1, x2, y2}
    __shared__ float  sarea[KK];        // gt area (inf if zero-area)
    __shared__ float  sroi[128 * 5];
    __shared__ float  sgtraw[KK * 5];

    const float* gtb = gt_in + (size_t)b * KK * 5;
    for (int i = tid; i < KK * 5; i += 128) sgtraw[i] = gtb[i];

    const int mbase = c * 128;
    if (mbase < NN) {   // stage this block's rois coalesced into shared
        const float* rb = rois_in + ((size_t)b * NN + mbase) * 5;
#pragma unroll
        for (int i = 0; i < 5; i++) sroi[tid + i * 128] = rb[tid + i * 128];
    }
    __syncthreads();

    {
        float x1 = sgtraw[tid * 5 + 0];
        float y1 = sgtraw[tid * 5 + 1];
        float x2 = sgtraw[tid * 5 + 2];
        float y2 = sgtraw[tid * 5 + 3];
        float gw = x2 - x1 + 1.0f;
        float gh = y2 - y1 + 1.0f;
        float a  = gw * gh;
        if (gw == 1.0f && gh == 1.0f) a = __int_as_float(0x7f800000);
        sbox[tid]  = make_float4(x1, y1, x2, y2);
        sarea[tid] = a;
    }
    __syncthreads();

    const int m = mbase + tid;          // always < MM (65*128 == MM)

    float x1, y1, x2, y2;
    if (m < NN) {
        const int li = tid * 5;
        x1 = sroi[li + 1]; y1 = sroi[li + 2];
        x2 = sroi[li + 3]; y2 = sroi[li + 4];
    } else {
        float4 g = sbox[m - NN];
        x1 = g.x; y1 = g.y; x2 = g.z; y2 = g.w;
    }

    const float aw = x2 - x1 + 1.0f;
    const float ah = y2 - y1 + 1.0f;
    const float areaA = aw * ah;
    const bool  az = (aw == 1.0f) && (ah == 1.0f);

    // 4 independent (num, den, k) chains; sentinel ov = -1 always replaced.
    float n0 = -1.0f, d0 = 1.0f, n1 = -1.0f, d1 = 1.0f;
    float n2 = -1.0f, d2 = 1.0f, n3 = -1.0f, d3 = 1.0f;
    int   k0 = 0, k1 = 1, k2 = 2, k3 = 3;

#pragma unroll 4
    for (int k = 0; k < KK; k += 4) {
#pragma unroll
        for (int j = 0; j < 4; j++) {
            const float4 g  = sbox[k + j];
            const float  ga = sarea[k + j];
            float iw = fminf(x2, g.z) - fmaxf(x1, g.x) + 1.0f;
            float ih = fminf(y2, g.w) - fmaxf(y1, g.y) + 1.0f;
            iw = fmaxf(iw, 0.0f);
            ih = fmaxf(ih, 0.0f);
            const float inter = iw * ih;
            const float den = areaA + ga - inter;
            if (j == 0) { if (inter * d0 > n0 * den) { n0 = inter; d0 = den; k0 = k;     } }
            if (j == 1) { if (inter * d1 > n1 * den) { n1 = inter; d1 = den; k1 = k + 1; } }
            if (j == 2) { if (inter * d2 > n2 * den) { n2 = inter; d2 = den; k2 = k + 2; } }
            if (j == 3) { if (inter * d3 > n3 * den) { n3 = inter; d3 = den; k3 = k + 3; } }
        }
    }

    // merge chains: strictly greater, or exact tie -> smaller k (first max)
    {
        const float p10 = n1 * d0, p01 = n0 * d1;
        if (p10 > p01 || (p10 == p01 && k1 < k0)) { n0 = n1; d0 = d1; k0 = k1; }
        const float p32 = n3 * d2, p23 = n2 * d3;
        if (p32 > p23 || (p32 == p23 && k3 < k2)) { n2 = n3; d2 = d3; k2 = k3; }
        const float p20 = n2 * d0, p02 = n0 * d2;
        if (p20 > p02 || (p20 == p02 && k2 < k0)) { n0 = n2; d0 = d2; k0 = k2; }
    }

    // single IEEE divide -> exact reference quotient for the winner
    float bst = n0 / d0;
    int   kk_ = k0;
    if (az) { bst = -1.0f; kk_ = 0; }
    const bool fg = (bst >= 0.5f);

    g_combo[b * MM + m] = kk_ | (fg ? 256 : 0);
    const float focal = fg ? (1.0f - bst) * (1.0f - bst) : 0.0f;
    const float ow    = (focal > 0.0f) ? 1.0f : 0.0f;
    out_inw [(size_t)b * MM + m] = make_float4(focal, focal, focal, focal);
    out_outw[(size_t)b * MM + m] = make_float4(ow, ow, ow, ow);

    // per-warp (= per-32-roi chunk) fg count; chunk = 4c + w covers 0..259
    const unsigned bal = __ballot_sync(FULLMASK, fg);
    if (lane == 0) g_cnt[b * NCH + c * 4 + w] = __popc(bal);
}

// ---------------------------------------------------------------------------
// K2: parallel scatter with LOCAL scan. One block = (batch b, 256-roi range).
// Warp 0 scans the 260 chunk counts (9 warp-scan rounds), keeps the 8
// prefixes this block needs + the batch total; then all warps scatter using
// g_off-equivalent from shared. Warp == 32-roi chunk -> in-warp ballot prefix.
// ---------------------------------------------------------------------------
__global__ void __launch_bounds__(256)
ptl_scatter_kernel(const float* __restrict__ rois_in,  // (B,N,5)
                   const float* __restrict__ gt_in,    // (B,K,5)
                   float* __restrict__ out_rois,       // (B,M,5)
                   float* __restrict__ out_lab,        // (B,M)
                   float4* __restrict__ out_tgt)       // (B,M) float4
{
    const int b    = blockIdx.y;
    const int c    = blockIdx.x;     // 0..32
    const int tid  = threadIdx.x;
    const int lane = tid & 31;
    const int w    = tid >> 5;

    __shared__ float sgt[KK * 5];
    __shared__ float sroi[256 * 5];
    __shared__ int   s_choff[8];     // exclusive fg prefix for our 8 chunks
    __shared__ int   s_tot;

    const float* gtb = gt_in + (size_t)b * KK * 5;
    for (int i = tid; i < KK * 5; i += 256) sgt[i] = gtb[i];

    const int mbase = c * 256;
    {
        int lim = (NN - mbase) * 5;
        if (lim > 256 * 5) lim = 256 * 5;
        if (lim < 0) lim = 0;
        const float* rb = rois_in + ((size_t)b * NN + mbase) * 5;
        for (int i = tid; i < lim; i += 256) sroi[i] = rb[i];
    }

    // warp 0: local scan over the batch's 260 chunk counts
    if (w == 0) {
        int carry = 0;
        const int lo = c * 8, hi = c * 8 + 8;
        for (int base = 0; base < NCH; base += 32) {
            const int idx = base + lane;
            int v = (idx < NCH) ? g_cnt[b * NCH + idx] : 0;
            int s = v;
#pragma unroll
            for (int off = 1; off < 32; off <<= 1) {
                int t = __shfl_up_sync(FULLMASK, s, off);
                if (lane >= off) s += t;
            }
            if (idx >= lo && idx < hi) s_choff[idx - lo] = carry + s - v;
            carry += __shfl_sync(FULLMASK, s, 31);
        }
        if (lane == 0) s_tot = carry;
    }
    __syncthreads();

    const int m = mbase + tid;
    int combo = 0, flag = 0;
    if (m < MM) {
        combo = g_combo[b * MM + m];
        flag  = (combo >> 8) & 1;
    }

    const unsigned bal = __ballot_sync(FULLMASK, flag != 0);
    const int wpre = __popc(bal & ((1u << lane) - 1u));

    if (m < MM) {
        const int prefix = s_choff[w] + wpre;   // #fg in [0, m)
        const int totfg  = s_tot;
        const int bestk  = combo & 255;
        const int dest   = flag ? prefix : (totfg + (m - prefix));

        float x1, y1, x2, y2;
        if (m < NN) {
            const int li = tid * 5;
            x1 = sroi[li + 1]; y1 = sroi[li + 2];
            x2 = sroi[li + 3]; y2 = sroi[li + 4];
        } else {
            const float* g = &sgt[(m - NN) * 5];
            x1 = g[0]; y1 = g[1]; x2 = g[2]; y2 = g[3];
        }

        const size_t ro = ((size_t)b * MM + dest) * 5;
        out_rois[ro + 0] = (float)b;
        out_rois[ro + 1] = x1;
        out_rois[ro + 2] = y1;
        out_rois[ro + 3] = x2;
        out_rois[ro + 4] = y2;

        const float cls = sgt[bestk * 5 + 4];
        const float lab = flag ? cls : 0.0f;
        out_lab[(size_t)b * MM + dest] = lab;

        float t0 = 0.0f, t1 = 0.0f, t2 = 0.0f, t3 = 0.0f;
        if (lab > 0.0f) {
            const float gx1 = sgt[bestk * 5 + 0];
            const float gy1 = sgt[bestk * 5 + 1];
            const float gx2 = sgt[bestk * 5 + 2];
            const float gy2 = sgt[bestk * 5 + 3];
            const float ew  = x2 - x1 + 1.0f;
            const float eh  = y2 - y1 + 1.0f;
            const float ecx = x1 + 0.5f * ew;
            const float ecy = y1 + 0.5f * eh;
            const float gw  = gx2 - gx1 + 1.0f;
            const float gh  = gy2 - gy1 + 1.0f;
            const float gcx = gx1 + 0.5f * gw;
            const float gcy = gy1 + 0.5f * gh;
            t0 = ((gcx - ecx) / ew) / 0.1f;
            t1 = ((gcy - ecy) / eh) / 0.1f;
            t2 = logf(gw / ew) / 0.2f;
            t3 = logf(gh / eh) / 0.2f;
        }
        out_tgt[(size_t)b * MM + dest] = make_float4(t0, t1, t2, t3);
    }
}

// ---------------------------------------------------------------------------
extern "C" void kernel_launch(void* const* d_in, const int* in_sizes, int n_in,
                              void* d_out, int out_size)
{
    const float* rois = (const float*)d_in[0];   // (16, 8192, 5) f32
    const float* gt   = (const float*)d_in[1];   // (16, 128, 5) f32
    float* out = (float*)d_out;

    // outputs concatenated in reference tuple order
    float* out_rois = out;                                   // B*M*5
    float* out_lab  = out_rois + (size_t)BB * MM * 5;        // B*M
    float* out_tgt  = out_lab  + (size_t)BB * MM;            // B*M*4
    float* out_inw  = out_tgt  + (size_t)BB * MM * 4;        // B*M*4
    float* out_outw = out_inw  + (size_t)BB * MM * 4;        // B*M*4

    dim3 g1(65, BB);
    ptl_iou_kernel<<<g1, 128>>>(rois, gt, (float4*)out_inw,
                                (float4*)out_outw);
    dim3 g2(33, BB);
    ptl_scatter_kernel<<<g2, 256>>>(rois, gt, out_rois, out_lab,
                                    (float4*)out_tgt);
}